// round 10
// baseline (speedup 1.0000x reference)
#include <cuda_runtime.h>
#include <math.h>

#define N_NODES 50000
#define N_EDGES 800000
#define HID 128
#define ANF 32
#define EPSV 1e-12f

typedef unsigned long long ull;

// -------- scratch --------
__device__ float g_hA[N_NODES * HID];
__device__ float g_hB[N_NODES * HID];
__device__ float g_sum[N_NODES * HID];
__device__ float g_cnt[N_NODES];

// -------- packed f32x2 helpers (FFMA2 is PTX-only) --------
__device__ __forceinline__ ull pack2(float x, float y) {
    ull r;
    asm("mov.b64 %0,{%1,%2};" : "=l"(r) : "r"(__float_as_uint(x)), "r"(__float_as_uint(y)));
    return r;
}
__device__ __forceinline__ ull dup2(float x) {
    ull r;
    asm("mov.b64 %0,{%1,%1};" : "=l"(r) : "r"(__float_as_uint(x)));
    return r;
}
__device__ __forceinline__ float2 unpack2(ull v) {
    unsigned a, b;
    asm("mov.b64 {%0,%1},%2;" : "=r"(a), "=r"(b) : "l"(v));
    return make_float2(__uint_as_float(a), __uint_as_float(b));
}
__device__ __forceinline__ ull fma2(ull a, ull b, ull c) {
    ull d;
    asm("fma.rn.f32x2 %0,%1,%2,%3;" : "=l"(d) : "l"(a), "l"(b), "l"(c));
    return d;
}
__device__ __forceinline__ void red_add_v4(float* p, float4 v) {
    asm volatile("red.global.add.v4.f32 [%0], {%1,%2,%3,%4};"
                 :: "l"(p), "f"(v.x), "f"(v.y), "f"(v.z), "f"(v.w) : "memory");
}
__device__ __forceinline__ float silu(float x) {
    return __fdividef(x, 1.0f + __expf(-x));
}

#define WSTR 132
#define HQS  20

// ============================================================================
// Kernel 1 (R7 best-measured config): hA = h @ W1a, hB = h @ W1b.
// 256 threads = 256 output cols, 16 nodes per pass, 8 accumulators.
// ============================================================================
#define HAB_SMEM_FLOATS (256 * WSTR + HID * HQS)
__global__ void __launch_bounds__(256, 1)
hab_kernel(const float* __restrict__ h,
           const float* __restrict__ e_w1,
           float* __restrict__ hA, float* __restrict__ hB) {
    extern __shared__ float s[];
    float* wT = s;                 // 256*132 [t][k]
    float* hq = wT + 256 * WSTR;   // 128*20  [k][m]
    const int tid = threadIdx.x;
    const int tl = tid & 127;

    for (int i = tid; i < 2 * HID * HID; i += 256) {
        const int tt = i & 127, kk = (i >> 7) & 127, half = i >> 14;
        wT[(half * HID + tt) * WSTR + kk] = e_w1[(kk + half * HID) * HID + tt];
    }
    __syncthreads();

    float* dst = (tid < HID) ? hA : hB;
    const int ngroups = N_NODES / 16;  // 3125
    for (int g = blockIdx.x; g < ngroups; g += gridDim.x) {
        const int nb = g * 16;
        for (int idx = tid; idx < 16 * HID; idx += 256) {
            const float v = h[nb * HID + idx];
            const int m = idx >> 7, k = idx & 127;
            hq[k * HQS + m] = v;
        }
        __syncthreads();

        ull a[8];
#pragma unroll
        for (int i = 0; i < 8; i++) a[i] = 0ull;
#pragma unroll 4
        for (int k = 0; k < HID; k += 4) {
            const float4 wv = *(const float4*)&wT[tid * WSTR + k];
#pragma unroll
            for (int j = 0; j < 4; j++) {
                const float wj = j == 0 ? wv.x : j == 1 ? wv.y : j == 2 ? wv.z : wv.w;
                const ull wp = dup2(wj);
                const ulonglong2* hp = (const ulonglong2*)&hq[(k + j) * HQS];
                const ulonglong2 q0 = hp[0], q1 = hp[1], q2 = hp[2], q3 = hp[3];
                a[0] = fma2(q0.x, wp, a[0]); a[1] = fma2(q0.y, wp, a[1]);
                a[2] = fma2(q1.x, wp, a[2]); a[3] = fma2(q1.y, wp, a[3]);
                a[4] = fma2(q2.x, wp, a[4]); a[5] = fma2(q2.y, wp, a[5]);
                a[6] = fma2(q3.x, wp, a[6]); a[7] = fma2(q3.y, wp, a[7]);
            }
        }
#pragma unroll
        for (int i = 0; i < 8; i++) {
            const float2 f = unpack2(a[i]);
            dst[(nb + 2 * i + 0) * HID + tl] = f.x;
            dst[(nb + 2 * i + 1) * HID + tl] = f.y;
        }
        __syncthreads();
    }
}

// ============================================================================
// Kernel 2: edge MLP + scatter.  512 threads, 64 edges/group, 1 CTA/SM.
// Warp map: fh = lane&15 (features 4fh..+3 of a 64-feature half),
//           epair = lane>>4 (edge quad), half = (tid>>5)&1, oct = tid>>6.
// Half-warps share weight addresses -> LDS dedup (2 wf/warp/k for weights).
// Activations stored DUPLICATED [k][2e]=(v,v): f32x2 act operands come
// straight out of LDS.128 halves; no dup-MOVs in inner loops.
// ============================================================================
#define EG 64
#define ADS 132   // duplicated-activation row stride (floats)
#define EDGE_SMEM_FLOATS (HID * HID + ANF * HID + ANF * ADS + HID * ADS)
__global__ void __launch_bounds__(512, 1)
edge_kernel(const float* __restrict__ hA, const float* __restrict__ hB,
            const int* __restrict__ row_idx, const int* __restrict__ col_idx,
            const float* __restrict__ edge_attr,
            const float* __restrict__ e_w1,   // W1c at rows 256..287
            const float* __restrict__ e_b1,
            const float* __restrict__ e_w2,
            const float* __restrict__ e_b2,
            float* __restrict__ gsum, float* __restrict__ gcnt) {
    extern __shared__ float s[];
    float* w2s      = s;                      // 128*128 [k][f] (raw e_w2)
    float* w1s      = w2s + HID * HID;        // 32*128  [k][f] (raw W1c)
    float* attr_dup = w1s + ANF * HID;        // 32*132  [k][2e] dup pairs
    float* ef1_dup  = attr_dup + ANF * ADS;   // 128*132 [k][2e] dup pairs
    const int tid   = threadIdx.x;
    const int lane  = tid & 31;
    const int fh    = lane & 15;       // feature group within half
    const int epair = lane >> 4;       // which edge quad of the octet
    const int half  = (tid >> 5) & 1;  // feature half (0: f<64, 1: f>=64)
    const int oct   = tid >> 6;        // edge octet 0..7
    const int fbase = 64 * half + 4 * fh;       // 4 features
    const int ecol  = 2 * (8 * oct + 4 * epair); // dup-column base (floats)

    for (int i = tid; i < HID * HID; i += 512) w2s[i] = e_w2[i];
    for (int i = tid; i < ANF * HID; i += 512) w1s[i] = e_w1[2 * HID * HID + i];
    const float4 b1v = *(const float4*)&e_b1[fbase];
    const float4 b2v = *(const float4*)&e_b2[fbase];
    __syncthreads();

    const int ngroups = N_EDGES / EG;  // 12500
    for (int g = blockIdx.x; g < ngroups; g += gridDim.x) {
        const int e0g = g * EG;
        int rowv[4], colv[4];
#pragma unroll
        for (int e = 0; e < 4; e++) {
            rowv[e] = row_idx[e0g + 8 * oct + 4 * epair + e];
            colv[e] = col_idx[e0g + 8 * oct + 4 * epair + e];
        }
        // stage edge_attr duplicated: coalesced LDG, STS.64 (v,v)
        for (int idx = tid; idx < EG * ANF; idx += 512) {
            const float v = edge_attr[e0g * ANF + idx];
            const int e = idx >> 5, k = idx & 31;
            *(ull*)&attr_dup[k * ADS + 2 * e] = dup2(v);
        }
        __syncthreads();                                            // (a)

        if (tid < EG) atomicAdd(&gcnt[row_idx[e0g + tid]], 1.0f);

        // -------- layer 1: pre = hA[row] + hB[col] + b1 ; += attr @ W1c ----
        ull accL[8];  // [cpair 01/23][e]
#pragma unroll
        for (int e = 0; e < 4; e++) {
            const float4 gA = *(const float4*)&hA[rowv[e] * HID + fbase];
            const float4 gB = *(const float4*)&hB[colv[e] * HID + fbase];
            accL[e]     = pack2(gA.x + gB.x + b1v.x, gA.y + gB.y + b1v.y);
            accL[4 + e] = pack2(gA.z + gB.z + b1v.z, gA.w + gB.w + b1v.w);
        }
#pragma unroll 8
        for (int k = 0; k < ANF; k++) {
            const float4 wv = *(const float4*)&w1s[k * HID + fbase];
            const ull w01 = pack2(wv.x, wv.y);
            const ull w23 = pack2(wv.z, wv.w);
            const ulonglong2 qa = *(const ulonglong2*)&attr_dup[k * ADS + ecol];
            const ulonglong2 qb = *(const ulonglong2*)&attr_dup[k * ADS + ecol + 4];
            accL[0] = fma2(w01, qa.x, accL[0]); accL[4] = fma2(w23, qa.x, accL[4]);
            accL[1] = fma2(w01, qa.y, accL[1]); accL[5] = fma2(w23, qa.y, accL[5]);
            accL[2] = fma2(w01, qb.x, accL[2]); accL[6] = fma2(w23, qb.x, accL[6]);
            accL[3] = fma2(w01, qb.y, accL[3]); accL[7] = fma2(w23, qb.y, accL[7]);
        }
        {
            float sv[4][4];  // [c][e]
#pragma unroll
            for (int e = 0; e < 4; e++) {
                const float2 f0 = unpack2(accL[e]);
                const float2 f1 = unpack2(accL[4 + e]);
                sv[0][e] = silu(f0.x);
                sv[1][e] = silu(f0.y);
                sv[2][e] = silu(f1.x);
                sv[3][e] = silu(f1.y);
            }
#pragma unroll
            for (int c = 0; c < 4; c++) {
                float* dst = &ef1_dup[(fbase + c) * ADS + ecol];
                *(float4*)dst       = make_float4(sv[c][0], sv[c][0], sv[c][1], sv[c][1]);
                *(float4*)(dst + 4) = make_float4(sv[c][2], sv[c][2], sv[c][3], sv[c][3]);
            }
        }
        __syncthreads();                                            // (b)

        // -------- layer 2 --------
        ull acc[8];
#pragma unroll
        for (int e = 0; e < 4; e++) {
            acc[e]     = pack2(b2v.x, b2v.y);
            acc[4 + e] = pack2(b2v.z, b2v.w);
        }
#pragma unroll 16
        for (int k = 0; k < HID; k++) {
            const float4 wv = *(const float4*)&w2s[k * HID + fbase];
            const ull w01 = pack2(wv.x, wv.y);
            const ull w23 = pack2(wv.z, wv.w);
            const ulonglong2 qa = *(const ulonglong2*)&ef1_dup[k * ADS + ecol];
            const ulonglong2 qb = *(const ulonglong2*)&ef1_dup[k * ADS + ecol + 4];
            acc[0] = fma2(w01, qa.x, acc[0]); acc[4] = fma2(w23, qa.x, acc[4]);
            acc[1] = fma2(w01, qa.y, acc[1]); acc[5] = fma2(w23, qa.y, acc[5]);
            acc[2] = fma2(w01, qb.x, acc[2]); acc[6] = fma2(w23, qb.x, acc[6]);
            acc[3] = fma2(w01, qb.y, acc[3]); acc[7] = fma2(w23, qb.y, acc[7]);
        }
        // epilogue: silu + per-edge vector reduction
#pragma unroll
        for (int e = 0; e < 4; e++) {
            const float2 f0 = unpack2(acc[e]);
            const float2 f1 = unpack2(acc[4 + e]);
            red_add_v4(&gsum[rowv[e] * HID + fbase],
                       make_float4(silu(f0.x), silu(f0.y), silu(f1.x), silu(f1.y)));
        }
        // next group's smem writes are ordered by (a)/(b)
    }
}

// ============================================================================
// Kernel 3 (R7 config): scatter-mean + node MLPs + Gram-Schmidt.
// 256 threads (t<128 branch1, else branch2), 16 nodes per pass.
// ============================================================================
#define HSTRIDE 129
#define NODE_SMEM_FLOATS (256 * WSTR + HID * HQS + 32 * HSTRIDE + 2 * 384 + 256 + 8 + 96)
__global__ void __launch_bounds__(256, 1)
node_kernel(const float* __restrict__ gsum, const float* __restrict__ gcnt,
            const float* __restrict__ v1_w1, const float* __restrict__ v1_b1,
            const float* __restrict__ v1_w2, const float* __restrict__ v1_b2,
            const float* __restrict__ v2_w1, const float* __restrict__ v2_b1,
            const float* __restrict__ v2_w2, const float* __restrict__ v2_b2,
            float* __restrict__ out) {
    extern __shared__ float s[];
    float* wT   = s;
    float* nq   = wT + 256 * WSTR;
    float* hid  = nq + HID * HQS;
    float* w2a  = hid + 32 * HSTRIDE;
    float* w2b  = w2a + 384;
    float* sb   = w2b + 384;
    float* b2ab = sb + 256;
    float* vecs = b2ab + 8;
    const int tid = threadIdx.x;
    const int tl = tid & 127;

    for (int i = tid; i < HID * HID; i += 256) {
        const int tt = i & 127, kk = i >> 7;
        wT[tt * WSTR + kk] = v1_w1[kk * HID + tt];
        wT[(HID + tt) * WSTR + kk] = v2_w1[kk * HID + tt];
    }
    for (int i = tid; i < 384; i += 256) { w2a[i] = v1_w2[i]; w2b[i] = v2_w2[i]; }
    if (tid < 128) { sb[tid] = v1_b1[tid]; sb[tid + 128] = v2_b1[tid]; }
    if (tid < 3)   { b2ab[tid] = v1_b2[tid]; b2ab[4 + tid] = v2_b2[tid]; }
    __syncthreads();

    const float myb = sb[tid];
    const int ngroups = N_NODES / 16;  // 3125
    for (int g = blockIdx.x; g < ngroups; g += gridDim.x) {
        const int nb = g * 16;
        for (int idx = tid; idx < 16 * HID; idx += 256) {
            const int m = idx >> 7, k = idx & 127;
            const float v = gsum[nb * HID + idx] / fmaxf(gcnt[nb + m], 1.0f);
            nq[k * HQS + m] = v;
        }
        __syncthreads();

        ull a[8];
#pragma unroll
        for (int i = 0; i < 8; i++) a[i] = dup2(myb);
#pragma unroll 4
        for (int k = 0; k < HID; k += 4) {
            const float4 wv = *(const float4*)&wT[tid * WSTR + k];
#pragma unroll
            for (int j = 0; j < 4; j++) {
                const float wj = j == 0 ? wv.x : j == 1 ? wv.y : j == 2 ? wv.z : wv.w;
                const ull wp = dup2(wj);
                const ulonglong2* hp = (const ulonglong2*)&nq[(k + j) * HQS];
                const ulonglong2 q0 = hp[0], q1 = hp[1], q2 = hp[2], q3 = hp[3];
                a[0] = fma2(q0.x, wp, a[0]); a[1] = fma2(q0.y, wp, a[1]);
                a[2] = fma2(q1.x, wp, a[2]); a[3] = fma2(q1.y, wp, a[3]);
                a[4] = fma2(q2.x, wp, a[4]); a[5] = fma2(q2.y, wp, a[5]);
                a[6] = fma2(q3.x, wp, a[6]); a[7] = fma2(q3.y, wp, a[7]);
            }
        }
        {
            const int br = tid >> 7;
#pragma unroll
            for (int i = 0; i < 8; i++) {
                const float2 f = unpack2(a[i]);
                hid[((2 * i + 0) * 2 + br) * HSTRIDE + tl] = silu(f.x);
                hid[((2 * i + 1) * 2 + br) * HSTRIDE + tl] = silu(f.y);
            }
        }
        __syncthreads();

        if (tid < 96) {
            const int m = tid / 6, r = tid % 6, br = r / 3, j = r % 3;
            const float* hh = &hid[(m * 2 + br) * HSTRIDE];
            const float* ww = br ? w2b : w2a;
            float acc = b2ab[br * 4 + j];
#pragma unroll 8
            for (int tt = 0; tt < HID; tt++) acc += hh[tt] * ww[tt * 3 + j];
            vecs[m * 6 + r] = acc;
        }
        __syncthreads();

        if (tid < 16) {
            const float* v = &vecs[tid * 6];
            float v1x = v[0], v1y = v[1], v1z = v[2];
            float v2x = v[3], v2y = v[4], v2z = v[5];
            float n1 = fmaxf(sqrtf(v1x * v1x + v1y * v1y + v1z * v1z), EPSV);
            v1x /= n1; v1y /= n1; v1z /= n1;
            const float d = v2x * v1x + v2y * v1y + v2z * v1z;
            v2x -= d * v1x; v2y -= d * v1y; v2z -= d * v1z;
            float n2 = fmaxf(sqrtf(v2x * v2x + v2y * v2y + v2z * v2z), EPSV);
            v2x /= n2; v2y /= n2; v2z /= n2;
            const float cx = v1y * v2z - v1z * v2y;
            const float cy = v1z * v2x - v1x * v2z;
            const float cz = v1x * v2y - v1y * v2x;
            float* o = &out[(size_t)(nb + tid) * 9];
            o[0] = v1x; o[1] = v2x; o[2] = cx;
            o[3] = v1y; o[4] = v2y; o[5] = cy;
            o[6] = v1z; o[7] = v2z; o[8] = cz;
        }
        __syncthreads();
    }
}

// ============================================================================
// Launch
// ============================================================================
extern "C" void kernel_launch(void* const* d_in, const int* in_sizes, int n_in,
                              void* d_out, int out_size) {
    const float* h      = (const float*)d_in[0];
    const int*   eidx   = (const int*)d_in[2];
    const float* eattr  = (const float*)d_in[3];
    const float* e_w1   = (const float*)d_in[4];
    const float* e_b1   = (const float*)d_in[5];
    const float* e_w2   = (const float*)d_in[6];
    const float* e_b2   = (const float*)d_in[7];
    const float* v1_w1  = (const float*)d_in[8];
    const float* v1_b1  = (const float*)d_in[9];
    const float* v1_w2  = (const float*)d_in[10];
    const float* v1_b2  = (const float*)d_in[11];
    const float* v2_w1  = (const float*)d_in[12];
    const float* v2_b1  = (const float*)d_in[13];
    const float* v2_w2  = (const float*)d_in[14];
    const float* v2_b2  = (const float*)d_in[15];
    float* out = (float*)d_out;

    float *hA, *hB, *sum, *cnt;
    cudaGetSymbolAddress((void**)&hA, g_hA);
    cudaGetSymbolAddress((void**)&hB, g_hB);
    cudaGetSymbolAddress((void**)&sum, g_sum);
    cudaGetSymbolAddress((void**)&cnt, g_cnt);

    const int hab_smem  = HAB_SMEM_FLOATS * 4;
    const int edge_smem = EDGE_SMEM_FLOATS * 4;
    const int node_smem = NODE_SMEM_FLOATS * 4;
    cudaFuncSetAttribute(hab_kernel, cudaFuncAttributeMaxDynamicSharedMemorySize, hab_smem);
    cudaFuncSetAttribute(edge_kernel, cudaFuncAttributeMaxDynamicSharedMemorySize, edge_smem);
    cudaFuncSetAttribute(node_kernel, cudaFuncAttributeMaxDynamicSharedMemorySize, node_smem);

    cudaMemsetAsync(sum, 0, (size_t)N_NODES * HID * sizeof(float));
    cudaMemsetAsync(cnt, 0, (size_t)N_NODES * sizeof(float));

    hab_kernel<<<148, 256, hab_smem>>>(h, e_w1, hA, hB);
    edge_kernel<<<148, 512, edge_smem>>>(hA, hB, eidx, eidx + N_EDGES, eattr,
                                         e_w1, e_b1, e_w2, e_b2, sum, cnt);
    node_kernel<<<148, 256, node_smem>>>(sum, cnt,
                                         v1_w1, v1_b1, v1_w2, v1_b2,
                                         v2_w1, v2_b1, v2_w2, v2_b2, out);
}

// round 13
// speedup vs baseline: 1.3766x; 1.3766x over previous
#include <cuda_runtime.h>
#include <math.h>

#define N_NODES 50000
#define N_EDGES 800000
#define HID 128
#define ANF 32
#define EPSV 1e-12f

typedef unsigned long long ull;

// -------- scratch --------
__device__ float g_hA[N_NODES * HID];
__device__ float g_hB[N_NODES * HID];
__device__ float g_sum[N_NODES * HID];
__device__ float g_cnt[N_NODES];

// -------- packed f32x2 helpers (FFMA2 is PTX-only) --------
__device__ __forceinline__ ull pack2(float x, float y) {
    ull r;
    asm("mov.b64 %0,{%1,%2};" : "=l"(r) : "r"(__float_as_uint(x)), "r"(__float_as_uint(y)));
    return r;
}
__device__ __forceinline__ ull dup2(float x) {
    ull r;
    asm("mov.b64 %0,{%1,%1};" : "=l"(r) : "r"(__float_as_uint(x)));
    return r;
}
__device__ __forceinline__ float2 unpack2(ull v) {
    unsigned a, b;
    asm("mov.b64 {%0,%1},%2;" : "=r"(a), "=r"(b) : "l"(v));
    return make_float2(__uint_as_float(a), __uint_as_float(b));
}
__device__ __forceinline__ ull fma2(ull a, ull b, ull c) {
    ull d;
    asm("fma.rn.f32x2 %0,%1,%2,%3;" : "=l"(d) : "l"(a), "l"(b), "l"(c));
    return d;
}
__device__ __forceinline__ void red_add_v4(float* p, float4 v) {
    asm volatile("red.global.add.v4.f32 [%0], {%1,%2,%3,%4};"
                 :: "l"(p), "f"(v.x), "f"(v.y), "f"(v.z), "f"(v.w) : "memory");
}
__device__ __forceinline__ float silu(float x) {
    return __fdividef(x, 1.0f + __expf(-x));
}

#define WSTR 132
#define HQS  20

// ============================================================================
// Kernel 1 (R7 best-measured config): hA = h @ W1a, hB = h @ W1b.
// 256 threads = 256 output cols, 16 nodes per pass, 8 accumulators.
// ============================================================================
#define HAB_SMEM_FLOATS (256 * WSTR + HID * HQS)
__global__ void __launch_bounds__(256, 1)
hab_kernel(const float* __restrict__ h,
           const float* __restrict__ e_w1,
           float* __restrict__ hA, float* __restrict__ hB) {
    extern __shared__ float s[];
    float* wT = s;                 // 256*132 [t][k]
    float* hq = wT + 256 * WSTR;   // 128*20  [k][m]
    const int tid = threadIdx.x;
    const int tl = tid & 127;

    for (int i = tid; i < 2 * HID * HID; i += 256) {
        const int tt = i & 127, kk = (i >> 7) & 127, half = i >> 14;
        wT[(half * HID + tt) * WSTR + kk] = e_w1[(kk + half * HID) * HID + tt];
    }
    __syncthreads();

    float* dst = (tid < HID) ? hA : hB;
    const int ngroups = N_NODES / 16;  // 3125
    for (int g = blockIdx.x; g < ngroups; g += gridDim.x) {
        const int nb = g * 16;
        for (int idx = tid; idx < 16 * HID; idx += 256) {
            const float v = h[nb * HID + idx];
            const int m = idx >> 7, k = idx & 127;
            hq[k * HQS + m] = v;
        }
        __syncthreads();

        ull a[8];
#pragma unroll
        for (int i = 0; i < 8; i++) a[i] = 0ull;
#pragma unroll 4
        for (int k = 0; k < HID; k += 4) {
            const float4 wv = *(const float4*)&wT[tid * WSTR + k];
#pragma unroll
            for (int j = 0; j < 4; j++) {
                const float wj = j == 0 ? wv.x : j == 1 ? wv.y : j == 2 ? wv.z : wv.w;
                const ull wp = dup2(wj);
                const ulonglong2* hp = (const ulonglong2*)&hq[(k + j) * HQS];
                const ulonglong2 q0 = hp[0], q1 = hp[1], q2 = hp[2], q3 = hp[3];
                a[0] = fma2(q0.x, wp, a[0]); a[1] = fma2(q0.y, wp, a[1]);
                a[2] = fma2(q1.x, wp, a[2]); a[3] = fma2(q1.y, wp, a[3]);
                a[4] = fma2(q2.x, wp, a[4]); a[5] = fma2(q2.y, wp, a[5]);
                a[6] = fma2(q3.x, wp, a[6]); a[7] = fma2(q3.y, wp, a[7]);
            }
        }
#pragma unroll
        for (int i = 0; i < 8; i++) {
            const float2 f = unpack2(a[i]);
            dst[(nb + 2 * i + 0) * HID + tl] = f.x;
            dst[(nb + 2 * i + 1) * HID + tl] = f.y;
        }
        __syncthreads();
    }
}

// ============================================================================
// Kernel 2: edge MLP + scatter.  256 threads, 2 CTAs/SM, 64 edges/group.
// fg = lane (features 4fg..4fg+3), eslot = tid>>5 (edges 8*eslot..+7).
// Each thread: 4 features x 8 edges.  Weight LDS.128 feeds 16 FFMA2.
// Acts broadcast [k][e] (warp-uniform).  W1c streamed via __ldg (L1-hot).
// ============================================================================
#define EG 64
#define ESTR 68   // attr/ef1 row stride (64 + 4 pad, 16B-aligned)
#define EDGE_SMEM_FLOATS (HID * HID + ANF * ESTR + HID * ESTR)
__global__ void __launch_bounds__(256, 2)
edge_kernel(const float* __restrict__ hA, const float* __restrict__ hB,
            const int* __restrict__ row_idx, const int* __restrict__ col_idx,
            const float* __restrict__ edge_attr,
            const float* __restrict__ e_w1,   // W1c at rows 256..287
            const float* __restrict__ e_b1,
            const float* __restrict__ e_w2,
            const float* __restrict__ e_b2,
            float* __restrict__ gsum, float* __restrict__ gcnt) {
    extern __shared__ float s[];
    float* w2s    = s;                    // 128*128 [k][f] (raw e_w2)
    float* attr_t = w2s + HID * HID;      // 32*68   [k][e]
    float* ef1t   = attr_t + ANF * ESTR;  // 128*68  [k][e]
    const int tid = threadIdx.x;
    const int fg  = tid & 31;    // feature group: features 4fg..4fg+3
    const int eslot = tid >> 5;  // 0..7 -> edges 8*eslot..+7
    const int myE = 8 * eslot;
    const float* w1c = e_w1 + 2 * HID * HID;  // [32][128]

    for (int i = tid; i < HID * HID; i += 256) w2s[i] = e_w2[i];
    const float4 b1v = *(const float4*)&e_b1[4 * fg];
    const float4 b2v = *(const float4*)&e_b2[4 * fg];
    __syncthreads();

    const int ngroups = N_EDGES / EG;  // 12500
    for (int g = blockIdx.x; g < ngroups; g += gridDim.x) {
        const int e0g = g * EG;
        int rowv[8], colv[8];
#pragma unroll
        for (int e = 0; e < 8; e++) {
            rowv[e] = row_idx[e0g + myE + e];
            colv[e] = col_idx[e0g + myE + e];
        }
        // stage edge_attr: coalesced LDG, transposed STS
        for (int idx = tid; idx < EG * ANF; idx += 256) {
            const float v = edge_attr[e0g * ANF + idx];
            const int e = idx >> 5, k = idx & 31;
            attr_t[k * ESTR + e] = v;
        }
        __syncthreads();                                            // (a)

        if (tid < EG) atomicAdd(&gcnt[row_idx[e0g + tid]], 1.0f);

        // -------- layer 1: pre = hA[row] + hB[col] + b1 ; += attr @ W1c ----
        // accL[e]   = features (4fg, 4fg+1) of edge e
        // accL[8+e] = features (4fg+2, 4fg+3) of edge e
        ull accL[16];
#pragma unroll
        for (int e = 0; e < 8; e++) {
            const float4 gA = *(const float4*)&hA[rowv[e] * HID + 4 * fg];
            const float4 gB = *(const float4*)&hB[colv[e] * HID + 4 * fg];
            accL[e]     = pack2(gA.x + gB.x + b1v.x, gA.y + gB.y + b1v.y);
            accL[8 + e] = pack2(gA.z + gB.z + b1v.z, gA.w + gB.w + b1v.w);
        }
#pragma unroll 4
        for (int k = 0; k < ANF; k++) {
            const float4 wv = __ldg((const float4*)&w1c[k * HID + 4 * fg]);
            const ull w01 = pack2(wv.x, wv.y);
            const ull w23 = pack2(wv.z, wv.w);
            const float4 a0 = *(const float4*)&attr_t[k * ESTR + myE];
            const float4 a1 = *(const float4*)&attr_t[k * ESTR + myE + 4];
            accL[0] = fma2(w01, dup2(a0.x), accL[0]); accL[8]  = fma2(w23, dup2(a0.x), accL[8]);
            accL[1] = fma2(w01, dup2(a0.y), accL[1]); accL[9]  = fma2(w23, dup2(a0.y), accL[9]);
            accL[2] = fma2(w01, dup2(a0.z), accL[2]); accL[10] = fma2(w23, dup2(a0.z), accL[10]);
            accL[3] = fma2(w01, dup2(a0.w), accL[3]); accL[11] = fma2(w23, dup2(a0.w), accL[11]);
            accL[4] = fma2(w01, dup2(a1.x), accL[4]); accL[12] = fma2(w23, dup2(a1.x), accL[12]);
            accL[5] = fma2(w01, dup2(a1.y), accL[5]); accL[13] = fma2(w23, dup2(a1.y), accL[13]);
            accL[6] = fma2(w01, dup2(a1.z), accL[6]); accL[14] = fma2(w23, dup2(a1.z), accL[14]);
            accL[7] = fma2(w01, dup2(a1.w), accL[7]); accL[15] = fma2(w23, dup2(a1.w), accL[15]);
        }
        {
            // silu + store rows 4fg..4fg+3, cols myE..myE+7
            float sv[4][8];
#pragma unroll
            for (int e = 0; e < 8; e++) {
                const float2 f0 = unpack2(accL[e]);
                const float2 f1 = unpack2(accL[8 + e]);
                sv[0][e] = silu(f0.x);
                sv[1][e] = silu(f0.y);
                sv[2][e] = silu(f1.x);
                sv[3][e] = silu(f1.y);
            }
#pragma unroll
            for (int c = 0; c < 4; c++) {
                float* dst = &ef1t[(4 * fg + c) * ESTR + myE];
                *(float4*)dst       = make_float4(sv[c][0], sv[c][1], sv[c][2], sv[c][3]);
                *(float4*)(dst + 4) = make_float4(sv[c][4], sv[c][5], sv[c][6], sv[c][7]);
            }
        }
        __syncthreads();                                            // (b)

        // -------- layer 2 --------
        ull acc[16];
#pragma unroll
        for (int e = 0; e < 8; e++) {
            acc[e]     = pack2(b2v.x, b2v.y);
            acc[8 + e] = pack2(b2v.z, b2v.w);
        }
#pragma unroll 8
        for (int k = 0; k < HID; k++) {
            const float4 wv = *(const float4*)&w2s[k * HID + 4 * fg];
            const ull w01 = pack2(wv.x, wv.y);
            const ull w23 = pack2(wv.z, wv.w);
            const float4 a0 = *(const float4*)&ef1t[k * ESTR + myE];
            const float4 a1 = *(const float4*)&ef1t[k * ESTR + myE + 4];
            acc[0] = fma2(w01, dup2(a0.x), acc[0]); acc[8]  = fma2(w23, dup2(a0.x), acc[8]);
            acc[1] = fma2(w01, dup2(a0.y), acc[1]); acc[9]  = fma2(w23, dup2(a0.y), acc[9]);
            acc[2] = fma2(w01, dup2(a0.z), acc[2]); acc[10] = fma2(w23, dup2(a0.z), acc[10]);
            acc[3] = fma2(w01, dup2(a0.w), acc[3]); acc[11] = fma2(w23, dup2(a0.w), acc[11]);
            acc[4] = fma2(w01, dup2(a1.x), acc[4]); acc[12] = fma2(w23, dup2(a1.x), acc[12]);
            acc[5] = fma2(w01, dup2(a1.y), acc[5]); acc[13] = fma2(w23, dup2(a1.y), acc[13]);
            acc[6] = fma2(w01, dup2(a1.z), acc[6]); acc[14] = fma2(w23, dup2(a1.z), acc[14]);
            acc[7] = fma2(w01, dup2(a1.w), acc[7]); acc[15] = fma2(w23, dup2(a1.w), acc[15]);
        }
        // epilogue: silu + per-edge vector reduction
#pragma unroll
        for (int e = 0; e < 8; e++) {
            const float2 f0 = unpack2(acc[e]);
            const float2 f1 = unpack2(acc[8 + e]);
            red_add_v4(&gsum[rowv[e] * HID + 4 * fg],
                       make_float4(silu(f0.x), silu(f0.y), silu(f1.x), silu(f1.y)));
        }
        // next group's smem writes are ordered by (a)/(b)
    }
}

// ============================================================================
// Kernel 3 (R7 config): scatter-mean + node MLPs + Gram-Schmidt.
// 256 threads (t<128 branch1, else branch2), 16 nodes per pass.
// ============================================================================
#define HSTRIDE 129
#define NODE_SMEM_FLOATS (256 * WSTR + HID * HQS + 32 * HSTRIDE + 2 * 384 + 256 + 8 + 96)
__global__ void __launch_bounds__(256, 1)
node_kernel(const float* __restrict__ gsum, const float* __restrict__ gcnt,
            const float* __restrict__ v1_w1, const float* __restrict__ v1_b1,
            const float* __restrict__ v1_w2, const float* __restrict__ v1_b2,
            const float* __restrict__ v2_w1, const float* __restrict__ v2_b1,
            const float* __restrict__ v2_w2, const float* __restrict__ v2_b2,
            float* __restrict__ out) {
    extern __shared__ float s[];
    float* wT   = s;
    float* nq   = wT + 256 * WSTR;
    float* hid  = nq + HID * HQS;
    float* w2a  = hid + 32 * HSTRIDE;
    float* w2b  = w2a + 384;
    float* sb   = w2b + 384;
    float* b2ab = sb + 256;
    float* vecs = b2ab + 8;
    const int tid = threadIdx.x;
    const int tl = tid & 127;

    for (int i = tid; i < HID * HID; i += 256) {
        const int tt = i & 127, kk = i >> 7;
        wT[tt * WSTR + kk] = v1_w1[kk * HID + tt];
        wT[(HID + tt) * WSTR + kk] = v2_w1[kk * HID + tt];
    }
    for (int i = tid; i < 384; i += 256) { w2a[i] = v1_w2[i]; w2b[i] = v2_w2[i]; }
    if (tid < 128) { sb[tid] = v1_b1[tid]; sb[tid + 128] = v2_b1[tid]; }
    if (tid < 3)   { b2ab[tid] = v1_b2[tid]; b2ab[4 + tid] = v2_b2[tid]; }
    __syncthreads();

    const float myb = sb[tid];
    const int ngroups = N_NODES / 16;  // 3125
    for (int g = blockIdx.x; g < ngroups; g += gridDim.x) {
        const int nb = g * 16;
        for (int idx = tid; idx < 16 * HID; idx += 256) {
            const int m = idx >> 7, k = idx & 127;
            const float v = gsum[nb * HID + idx] / fmaxf(gcnt[nb + m], 1.0f);
            nq[k * HQS + m] = v;
        }
        __syncthreads();

        ull a[8];
#pragma unroll
        for (int i = 0; i < 8; i++) a[i] = dup2(myb);
#pragma unroll 4
        for (int k = 0; k < HID; k += 4) {
            const float4 wv = *(const float4*)&wT[tid * WSTR + k];
#pragma unroll
            for (int j = 0; j < 4; j++) {
                const float wj = j == 0 ? wv.x : j == 1 ? wv.y : j == 2 ? wv.z : wv.w;
                const ull wp = dup2(wj);
                const ulonglong2* hp = (const ulonglong2*)&nq[(k + j) * HQS];
                const ulonglong2 q0 = hp[0], q1 = hp[1], q2 = hp[2], q3 = hp[3];
                a[0] = fma2(q0.x, wp, a[0]); a[1] = fma2(q0.y, wp, a[1]);
                a[2] = fma2(q1.x, wp, a[2]); a[3] = fma2(q1.y, wp, a[3]);
                a[4] = fma2(q2.x, wp, a[4]); a[5] = fma2(q2.y, wp, a[5]);
                a[6] = fma2(q3.x, wp, a[6]); a[7] = fma2(q3.y, wp, a[7]);
            }
        }
        {
            const int br = tid >> 7;
#pragma unroll
            for (int i = 0; i < 8; i++) {
                const float2 f = unpack2(a[i]);
                hid[((2 * i + 0) * 2 + br) * HSTRIDE + tl] = silu(f.x);
                hid[((2 * i + 1) * 2 + br) * HSTRIDE + tl] = silu(f.y);
            }
        }
        __syncthreads();

        if (tid < 96) {
            const int m = tid / 6, r = tid % 6, br = r / 3, j = r % 3;
            const float* hh = &hid[(m * 2 + br) * HSTRIDE];
            const float* ww = br ? w2b : w2a;
            float acc = b2ab[br * 4 + j];
#pragma unroll 8
            for (int tt = 0; tt < HID; tt++) acc += hh[tt] * ww[tt * 3 + j];
            vecs[m * 6 + r] = acc;
        }
        __syncthreads();

        if (tid < 16) {
            const float* v = &vecs[tid * 6];
            float v1x = v[0], v1y = v[1], v1z = v[2];
            float v2x = v[3], v2y = v[4], v2z = v[5];
            float n1 = fmaxf(sqrtf(v1x * v1x + v1y * v1y + v1z * v1z), EPSV);
            v1x /= n1; v1y /= n1; v1z /= n1;
            const float d = v2x * v1x + v2y * v1y + v2z * v1z;
            v2x -= d * v1x; v2y -= d * v1y; v2z -= d * v1z;
            float n2 = fmaxf(sqrtf(v2x * v2x + v2y * v2y + v2z * v2z), EPSV);
            v2x /= n2; v2y /= n2; v2z /= n2;
            const float cx = v1y * v2z - v1z * v2y;
            const float cy = v1z * v2x - v1x * v2z;
            const float cz = v1x * v2y - v1y * v2x;
            float* o = &out[(size_t)(nb + tid) * 9];
            o[0] = v1x; o[1] = v2x; o[2] = cx;
            o[3] = v1y; o[4] = v2y; o[5] = cy;
            o[6] = v1z; o[7] = v2z; o[8] = cz;
        }
        __syncthreads();
    }
}

// ============================================================================
// Launch
// ============================================================================
extern "C" void kernel_launch(void* const* d_in, const int* in_sizes, int n_in,
                              void* d_out, int out_size) {
    const float* h      = (const float*)d_in[0];
    const int*   eidx   = (const int*)d_in[2];
    const float* eattr  = (const float*)d_in[3];
    const float* e_w1   = (const float*)d_in[4];
    const float* e_b1   = (const float*)d_in[5];
    const float* e_w2   = (const float*)d_in[6];
    const float* e_b2   = (const float*)d_in[7];
    const float* v1_w1  = (const float*)d_in[8];
    const float* v1_b1  = (const float*)d_in[9];
    const float* v1_w2  = (const float*)d_in[10];
    const float* v1_b2  = (const float*)d_in[11];
    const float* v2_w1  = (const float*)d_in[12];
    const float* v2_b1  = (const float*)d_in[13];
    const float* v2_w2  = (const float*)d_in[14];
    const float* v2_b2  = (const float*)d_in[15];
    float* out = (float*)d_out;

    float *hA, *hB, *sum, *cnt;
    cudaGetSymbolAddress((void**)&hA, g_hA);
    cudaGetSymbolAddress((void**)&hB, g_hB);
    cudaGetSymbolAddress((void**)&sum, g_sum);
    cudaGetSymbolAddress((void**)&cnt, g_cnt);

    const int hab_smem  = HAB_SMEM_FLOATS * 4;
    const int edge_smem = EDGE_SMEM_FLOATS * 4;
    const int node_smem = NODE_SMEM_FLOATS * 4;
    cudaFuncSetAttribute(hab_kernel, cudaFuncAttributeMaxDynamicSharedMemorySize, hab_smem);
    cudaFuncSetAttribute(edge_kernel, cudaFuncAttributeMaxDynamicSharedMemorySize, edge_smem);
    cudaFuncSetAttribute(node_kernel, cudaFuncAttributeMaxDynamicSharedMemorySize, node_smem);

    cudaMemsetAsync(sum, 0, (size_t)N_NODES * HID * sizeof(float));
    cudaMemsetAsync(cnt, 0, (size_t)N_NODES * sizeof(float));

    hab_kernel<<<148, 256, hab_smem>>>(h, e_w1, hA, hB);
    edge_kernel<<<296, 256, edge_smem>>>(hA, hB, eidx, eidx + N_EDGES, eattr,
                                         e_w1, e_b1, e_w2, e_b2, sum, cnt);
    node_kernel<<<148, 256, node_smem>>>(sum, cnt,
                                         v1_w1, v1_b1, v1_w2, v1_b2,
                                         v2_w1, v2_b1, v2_w2, v2_b2, out);
}